// round 9
// baseline (speedup 1.0000x reference)
#include <cuda_runtime.h>
#include <math.h>

// Problem constants (fixed by reference)
#define NN   100000
#define EE   1600000
#define BBg  256

// ---------------- device scratch (no allocations allowed) ----------------
__device__ float g_U[NN * 320];      // U_k = Hin @ W_k, concatenated (max 5*64 cols)
__device__ float g_bA[NN * 64];
__device__ float g_bB[NN * 64];
__device__ float g_bC[NN * 64];
__device__ float g_h1[NN * 32];
__device__ float g_h2[NN * 64];
__device__ float g_h3[NN * 64];
__device__ float g_wedge[EE];        // base edge weight
__device__ float g_wedge2[EE];       // 2x edge weight (Clenshaw inner steps)
__device__ float g_wdiag[NN];
__device__ float g_dis[NN];
__device__ int   g_deg[NN];
__device__ float g_Wc1[128 * 160];
__device__ float g_Wc2[32 * 320];
__device__ float g_Wc3[64 * 320];
__device__ float g_s[NN];
__device__ float g_se[NN];
__device__ unsigned g_smax[BBg];
__device__ float g_den[BBg];
__device__ float g_cnt[BBg];
__device__ float g_pool[BBg * 64];

// ---------------- small helpers ----------------
__device__ __forceinline__ unsigned f2o(float f) {
    unsigned u = __float_as_uint(f);
    return (u & 0x80000000u) ? ~u : (u | 0x80000000u);
}
__device__ __forceinline__ float o2f(unsigned k) {
    unsigned u = (k & 0x80000000u) ? (k & 0x7FFFFFFFu) : ~k;
    return __uint_as_float(u);
}

// ---------------- init (deg + pooling accumulators, one launch) ----------------
__global__ void k_init(int* deg, unsigned* smax, float* den, float* cnt, float* pool) {
    int i = blockIdx.x * blockDim.x + threadIdx.x;
    if (i < NN) deg[i] = 0;
    if (i < BBg) { smax[i] = 0u; den[i] = 0.f; cnt[i] = 0.f; }
    if (i < BBg * 64) pool[i] = 0.f;
}

// ---------------- graph normalization ----------------
__global__ void k_deg(const int* __restrict__ src, int* deg, int E) {
    int e = blockIdx.x * blockDim.x + threadIdx.x;
    if (e < E) atomicAdd(&deg[src[e]], 1);
}
__global__ void k_node(const int* __restrict__ batch, const float* __restrict__ lmax,
                       const int* __restrict__ deg, float* dis, float* wdiag, int n) {
    int i = blockIdx.x * blockDim.x + threadIdx.x;
    if (i >= n) return;
    int d = deg[i];
    dis[i] = (d > 0) ? rsqrtf((float)d) : 0.f;
    wdiag[i] = 2.f / lmax[batch[i]] - 1.f;
}
__global__ void k_edgew(const int* __restrict__ src, const int* __restrict__ dst,
                        const int* __restrict__ batch, const float* __restrict__ lmax,
                        const float* __restrict__ dis, float* we, float* we2, int E) {
    int e = blockIdx.x * blockDim.x + threadIdx.x;
    if (e >= E) return;
    int s = src[e];
    float w = -2.f * dis[s] * dis[dst[e]] / lmax[batch[s]];
    we[e] = w;
    we2[e] = 2.f * w;
}

// W[k][i][j] (K=5 leading) -> Wcat[i][k*Fout + j]
__global__ void k_reshape(const float* __restrict__ W, float* Wc, int Fin, int Fout) {
    int idx = blockIdx.x * blockDim.x + threadIdx.x;
    int tot = 5 * Fin * Fout;
    if (idx >= tot) return;
    int j = idx % Fout;
    int t = idx / Fout;
    int i = t % Fin;
    int k = t / Fin;
    Wc[i * (5 * Fout) + k * Fout + j] = W[idx];
}

// ---------------- SGEMM: C[M,Nc] = reluA?(relu(A)):A  @ B ----------------
#define BM 128
#define BN 32
#define BK 32
__global__ __launch_bounds__(256) void k_sgemm(const float* __restrict__ A,
                                               const float* __restrict__ B,
                                               float* __restrict__ C,
                                               int M, int K, int Nc, int reluA) {
    __shared__ float As[BK][BM + 4];
    __shared__ float Bs[BK][BN];
    int bm = blockIdx.y * BM, bn = blockIdx.x * BN;
    int tid = threadIdx.x;
    int ty = tid >> 4;      // 0..15, rows (x8)
    int tx = tid & 15;      // 0..15, cols (x2)
    float acc[8][2];
#pragma unroll
    for (int r = 0; r < 8; r++) { acc[r][0] = 0.f; acc[r][1] = 0.f; }

    for (int k0 = 0; k0 < K; k0 += BK) {
#pragma unroll
        for (int i = 0; i < 16; i++) {
            int idx = tid + i * 256;
            int m = idx >> 5;      // /32
            int k = idx & 31;
            int gm = bm + m;
            float v = (gm < M) ? A[(size_t)gm * K + k0 + k] : 0.f;
            As[k][m] = reluA ? fmaxf(v, 0.f) : v;
        }
#pragma unroll
        for (int i = 0; i < 4; i++) {
            int idx = tid + i * 256;
            int k = idx >> 5;      // /BN
            int c = idx & 31;
            Bs[k][c] = B[(size_t)(k0 + k) * Nc + bn + c];
        }
        __syncthreads();
#pragma unroll
        for (int kk = 0; kk < BK; kk++) {
            const float4* ap = (const float4*)&As[kk][ty * 8];
            float4 a0 = ap[0], a1 = ap[1];
            const float2* bp = (const float2*)&Bs[kk][tx * 2];
            float2 bv = bp[0];
            float a[8] = {a0.x, a0.y, a0.z, a0.w, a1.x, a1.y, a1.z, a1.w};
#pragma unroll
            for (int r = 0; r < 8; r++) {
                acc[r][0] += a[r] * bv.x;
                acc[r][1] += a[r] * bv.y;
            }
        }
        __syncthreads();
    }
#pragma unroll
    for (int r = 0; r < 8; r++) {
        int gm = bm + ty * 8 + r;
        if (gm < M) {
            float2 v; v.x = acc[r][0]; v.y = acc[r][1];
            *(float2*)&C[(size_t)gm * Nc + bn + tx * 2] = v;
        }
    }
}

// ---------------- Clenshaw: node-local combine (diag + poly terms) ----------------
// out[n,f] = U[n,f] + alpha*wdiag[n]*bcur[n,f] - bprev[n,f] (+ bias[f])
// F4 compile-time (8 or 16): div/mod become shift/mask.
template <int F4, bool HASP, bool HASB>
__global__ void k_combine(const float4* __restrict__ U, int us4,
                          const float4* __restrict__ bc, int bs4,
                          const float4* __restrict__ bp, int ps4,
                          const float* __restrict__ wdiag,
                          const float* __restrict__ bias,
                          float alpha, float4* __restrict__ out, int n) {
    int idx = blockIdx.x * blockDim.x + threadIdx.x;
    if (idx >= n * F4) return;
    int nd = idx / F4, q = idx - nd * F4;   // F4 is a power of two: compiles to shifts
    float4 u = U[(size_t)nd * us4 + q];
    float4 b = bc[(size_t)nd * bs4 + q];
    float w = alpha * wdiag[nd];
    float4 r;
    r.x = fmaf(w, b.x, u.x);
    r.y = fmaf(w, b.y, u.y);
    r.z = fmaf(w, b.z, u.z);
    r.w = fmaf(w, b.w, u.w);
    if (HASP) {
        float4 p = bp[(size_t)nd * ps4 + q];
        r.x -= p.x; r.y -= p.y; r.z -= p.z; r.w -= p.w;
    }
    if (HASB) {
        float4 bb = ((const float4*)bias)[q];
        r.x += bb.x; r.y += bb.y; r.z += bb.z; r.w += bb.w;
    }
    out[idx] = r;
}

// edge scatter: out[dst[e], :] += we[e] * b[src[e], :]  (weight prescaled)
// grid-stride; feature index fastest so F4 consecutive lanes read one
// contiguous source row (best coalescing for the random-row gather).
// F4 compile-time -> shift/mask indexing, no integer division in the loop.
template <int F4>
__global__ __launch_bounds__(256) void k_edge(const int* __restrict__ src,
                       const int* __restrict__ dst,
                       const float* __restrict__ we,
                       const float4* __restrict__ b, int bs4,
                       float* __restrict__ out, int E) {
    int tot = E * F4;
    for (int idx = blockIdx.x * blockDim.x + threadIdx.x; idx < tot;
         idx += gridDim.x * blockDim.x) {
        int e = idx / F4, q = idx & (F4 - 1);   // power-of-two: shift + mask
        float w = __ldg(&we[e]);
        float4 v = b[(size_t)__ldg(&src[e]) * bs4 + q];
        float* p = out + ((size_t)__ldg(&dst[e]) * F4 + q) * 4;
        asm volatile("red.global.add.v4.f32 [%0], {%1,%2,%3,%4};"
                     :: "l"(p), "f"(w * v.x), "f"(w * v.y), "f"(w * v.z), "f"(w * v.w)
                     : "memory");
    }
}

// ---------------- pooling ----------------
__global__ void k_score(const float4* __restrict__ cl4, const float* __restrict__ cw,
                        const float* __restrict__ cb, const int* __restrict__ batch,
                        float* s, unsigned* smax, int n) {
    int i = blockIdx.x * blockDim.x + threadIdx.x;
    if (i >= n) return;
    float acc = cb[0];
#pragma unroll
    for (int j = 0; j < 4; j++) {
        float4 c = cl4[i * 4 + j];
        acc += c.x * cw[j * 4 + 0] + c.y * cw[j * 4 + 1]
             + c.z * cw[j * 4 + 2] + c.w * cw[j * 4 + 3];
    }
    s[i] = acc;
    atomicMax(&smax[batch[i]], f2o(acc));
}
__global__ void k_exp(const float* __restrict__ s, const unsigned* __restrict__ smax,
                      const int* __restrict__ batch, float* se, float* den, float* cnt, int n) {
    int i = blockIdx.x * blockDim.x + threadIdx.x;
    if (i >= n) return;
    int b = batch[i];
    float e = expf(s[i] - o2f(smax[b]));
    se[i] = e;
    atomicAdd(&den[b], e);
    atomicAdd(&cnt[b], 1.f);
}
// weighted max pool; h is pre-relu layer-3 output, relu fused here.
// w >= 0 and relu(h) >= 0, so int-compare atomicMax on float bits is monotone
// (pool initialized to 0.0f which is also the relu lower bound).
__global__ void k_wmax(const float* __restrict__ se, const float* __restrict__ den,
                       const float* __restrict__ cnt, const int* __restrict__ batch,
                       const float4* __restrict__ h, int* pool, int n) {
    int idx = blockIdx.x * blockDim.x + threadIdx.x;  // n * 16 (F=64 -> 16 float4)
    if (idx >= n * 16) return;
    int nd = idx >> 4, q = idx & 15;
    int b = batch[nd];
    float w = se[nd] / den[b] * cnt[b];
    float4 v = h[(size_t)nd * 16 + q];
    v.x = fmaxf(v.x, 0.f); v.y = fmaxf(v.y, 0.f);
    v.z = fmaxf(v.z, 0.f); v.w = fmaxf(v.w, 0.f);
    int* p = pool + (b * 64 + q * 4);
    atomicMax(&p[0], __float_as_int(w * v.x));
    atomicMax(&p[1], __float_as_int(w * v.y));
    atomicMax(&p[2], __float_as_int(w * v.z));
    atomicMax(&p[3], __float_as_int(w * v.w));
}
__global__ void k_final(const float* __restrict__ pool, const float* __restrict__ a1w,
                        const float* __restrict__ a1b, const float* __restrict__ a2w,
                        const float* __restrict__ a2b, float* out) {
    int b = blockIdx.x * blockDim.x + threadIdx.x;
    if (b >= BBg) return;
    float acc = a2b[0];
#pragma unroll
    for (int j = 0; j < 16; j++) {
        float a = a1b[j];
#pragma unroll
        for (int f = 0; f < 64; f++) a += pool[b * 64 + f] * a1w[f * 16 + j];
        acc += fmaxf(a, 0.f) * a2w[j];
    }
    out[b] = acc;
}

// ---------------- per-layer Clenshaw driver (compile-time F4) ----------------
template <int F4>
static void run_layer_poly(const int* src, const int* dst,
                           const float* wedge, const float* wedge2,
                           const float* wdiag, const float* U,
                           float* bA, float* bB, float* bC,
                           const float* bias, float* Hout) {
    const int T = 256;
    const int EDGE_GRID = 148 * 8;
    const int C4 = 5 * F4;
    int nodeBl = (NN * F4 + T - 1) / T;
    const float4* U4 = (const float4*)U;

    // b4 = U4 (view). b3 = U3 + 2 L b4
    k_combine<F4, false, false><<<nodeBl, T>>>(U4 + 3 * F4, C4, U4 + 4 * F4, C4,
                                               nullptr, 0, wdiag, nullptr, 2.f,
                                               (float4*)bA, NN);
    k_edge<F4><<<EDGE_GRID, T>>>(src, dst, wedge2, U4 + 4 * F4, C4, bA, EE);
    // b2 = U2 + 2 L b3 - b4
    k_combine<F4, true, false><<<nodeBl, T>>>(U4 + 2 * F4, C4, (const float4*)bA, F4,
                                              U4 + 4 * F4, C4, wdiag, nullptr, 2.f,
                                              (float4*)bB, NN);
    k_edge<F4><<<EDGE_GRID, T>>>(src, dst, wedge2, (const float4*)bA, F4, bB, EE);
    // b1 = U1 + 2 L b2 - b3
    k_combine<F4, true, false><<<nodeBl, T>>>(U4 + 1 * F4, C4, (const float4*)bB, F4,
                                              (const float4*)bA, F4, wdiag, nullptr, 2.f,
                                              (float4*)bC, NN);
    k_edge<F4><<<EDGE_GRID, T>>>(src, dst, wedge2, (const float4*)bB, F4, bC, EE);
    // out = U0 + L b1 - b2 + bias (relu deferred to consumer)
    k_combine<F4, true, true><<<nodeBl, T>>>(U4, C4, (const float4*)bC, F4,
                                             (const float4*)bB, F4, wdiag, bias, 1.f,
                                             (float4*)Hout, NN);
    k_edge<F4><<<EDGE_GRID, T>>>(src, dst, wedge, (const float4*)bC, F4, Hout, EE);
}

// ---------------- host orchestration ----------------
extern "C" void kernel_launch(void* const* d_in, const int* in_sizes, int n_in,
                              void* d_out, int out_size) {
    const float* x     = (const float*)d_in[0];
    const float* cl    = (const float*)d_in[1];
    const float* lmax  = (const float*)d_in[2];
    const int*   src   = (const int*)d_in[3];
    const int*   dst   = (const int*)d_in[4];
    const int*   batch = (const int*)d_in[5];
    const float* w1 = (const float*)d_in[6];  const float* b1 = (const float*)d_in[7];
    const float* w2 = (const float*)d_in[8];  const float* b2 = (const float*)d_in[9];
    const float* w3 = (const float*)d_in[10]; const float* b3 = (const float*)d_in[11];
    const float* cw = (const float*)d_in[12]; const float* cb = (const float*)d_in[13];
    const float* a1w = (const float*)d_in[14]; const float* a1b = (const float*)d_in[15];
    const float* a2w = (const float*)d_in[16]; const float* a2b = (const float*)d_in[17];
    float* out = (float*)d_out;

    // Resolve scratch addresses every call (no static caching — harness rules).
    float *U, *bA, *bB, *bC, *h1, *h2, *h3, *wedge, *wedge2, *wdiag, *dis;
    float *Wc1, *Wc2, *Wc3, *s, *se, *den, *cnt, *pool;
    int* deg; unsigned* smax;
    cudaGetSymbolAddress((void**)&U, g_U);
    cudaGetSymbolAddress((void**)&bA, g_bA);
    cudaGetSymbolAddress((void**)&bB, g_bB);
    cudaGetSymbolAddress((void**)&bC, g_bC);
    cudaGetSymbolAddress((void**)&h1, g_h1);
    cudaGetSymbolAddress((void**)&h2, g_h2);
    cudaGetSymbolAddress((void**)&h3, g_h3);
    cudaGetSymbolAddress((void**)&wedge, g_wedge);
    cudaGetSymbolAddress((void**)&wedge2, g_wedge2);
    cudaGetSymbolAddress((void**)&wdiag, g_wdiag);
    cudaGetSymbolAddress((void**)&dis, g_dis);
    cudaGetSymbolAddress((void**)&deg, g_deg);
    cudaGetSymbolAddress((void**)&Wc1, g_Wc1);
    cudaGetSymbolAddress((void**)&Wc2, g_Wc2);
    cudaGetSymbolAddress((void**)&Wc3, g_Wc3);
    cudaGetSymbolAddress((void**)&s, g_s);
    cudaGetSymbolAddress((void**)&se, g_se);
    cudaGetSymbolAddress((void**)&smax, g_smax);
    cudaGetSymbolAddress((void**)&den, g_den);
    cudaGetSymbolAddress((void**)&cnt, g_cnt);
    cudaGetSymbolAddress((void**)&pool, g_pool);

    const int T = 256;

    // ---- graph norm precompute ----
    k_init<<<(NN + T - 1) / T, T>>>(deg, smax, den, cnt, pool);
    k_deg<<<(EE + T - 1) / T, T>>>(src, deg, EE);
    k_node<<<(NN + T - 1) / T, T>>>(batch, lmax, deg, dis, wdiag, NN);
    k_edgew<<<(EE + T - 1) / T, T>>>(src, dst, batch, lmax, dis, wedge, wedge2, EE);
    k_reshape<<<(5 * 128 * 32 + T - 1) / T, T>>>(w1, Wc1, 128, 32);
    k_reshape<<<(5 * 32 * 64 + T - 1) / T, T>>>(w2, Wc2, 32, 64);
    k_reshape<<<(5 * 64 * 64 + T - 1) / T, T>>>(w3, Wc3, 64, 64);

    // ---- layer 1: Fin=128, Fout=32 (F4=8) ----
    {
        dim3 gr(160 / BN, (NN + BM - 1) / BM);
        k_sgemm<<<gr, 256>>>(x, Wc1, U, NN, 128, 160, 0);
        run_layer_poly<8>(src, dst, wedge, wedge2, wdiag, U, bA, bB, bC, b1, h1);
    }
    // ---- layer 2: Fin=32, Fout=64 (F4=16); relu(h1) fused into GEMM read ----
    {
        dim3 gr(320 / BN, (NN + BM - 1) / BM);
        k_sgemm<<<gr, 256>>>(h1, Wc2, U, NN, 32, 320, 1);
        run_layer_poly<16>(src, dst, wedge, wedge2, wdiag, U, bA, bB, bC, b2, h2);
    }
    // ---- layer 3: Fin=64, Fout=64 (F4=16); relu(h2) fused into GEMM read ----
    {
        dim3 gr(320 / BN, (NN + BM - 1) / BM);
        k_sgemm<<<gr, 256>>>(h2, Wc3, U, NN, 64, 320, 1);
        run_layer_poly<16>(src, dst, wedge, wedge2, wdiag, U, bA, bB, bC, b3, h3);
    }

    // ---- pooling + head (relu(h3) fused into k_wmax) ----
    k_score<<<(NN + T - 1) / T, T>>>((const float4*)cl, cw, cb, batch, s, smax, NN);
    k_exp<<<(NN + T - 1) / T, T>>>(s, smax, batch, se, den, cnt, NN);
    k_wmax<<<(NN * 16 + T - 1) / T, T>>>(se, den, cnt, batch, (const float4*)h3,
                                         (int*)pool, NN);
    k_final<<<1, BBg>>>(pool, a1w, a1b, a2w, a2b, out);

    (void)in_sizes; (void)n_in; (void)out_size;
}

// round 17
// speedup vs baseline: 1.2047x; 1.2047x over previous
#include <cuda_runtime.h>
#include <math.h>

// Problem constants (fixed by reference)
#define NN   100000
#define EE   1600000
#define BBg  256

// ---------------- device scratch (no allocations allowed) ----------------
__device__ float g_U[NN * 320];      // U_k = Hin @ W_k, concatenated (max 5*64 cols)
__device__ float g_bA[NN * 64];
__device__ float g_bB[NN * 64];
__device__ float g_bC[NN * 64];
__device__ float g_h1[NN * 32];
__device__ float g_h2[NN * 64];
__device__ float g_h3[NN * 64];
__device__ float g_wedge[EE];        // base edge weight (per original edge id)
__device__ float g_wdiag[NN];
__device__ float g_dis[NN];
__device__ int   g_deg[NN];          // out-degree by src (normalization)
__device__ int   g_indeg[NN];        // in-degree by dst (CSR)
__device__ int   g_rowptr[NN + 1];   // CSR row pointers (by dst)
__device__ int   g_cursor[NN];       // scatter cursors
__device__ float2 g_ep[EE];          // CSR payload: (src as int bits, weight)
__device__ float g_Wc1[128 * 160];
__device__ float g_Wc2[32 * 320];
__device__ float g_Wc3[64 * 320];
__device__ float g_s[NN];
__device__ float g_se[NN];
__device__ unsigned g_smax[BBg];
__device__ float g_den[BBg];
__device__ float g_cnt[BBg];
__device__ float g_pool[BBg * 64];

// ---------------- small helpers ----------------
__device__ __forceinline__ unsigned f2o(float f) {
    unsigned u = __float_as_uint(f);
    return (u & 0x80000000u) ? ~u : (u | 0x80000000u);
}
__device__ __forceinline__ float o2f(unsigned k) {
    unsigned u = (k & 0x80000000u) ? (k & 0x7FFFFFFFu) : ~k;
    return __uint_as_float(u);
}

// ---------------- init (degrees + pooling accumulators, one launch) ----------------
__global__ void k_init(int* deg, int* indeg, unsigned* smax, float* den, float* cnt,
                       float* pool) {
    int i = blockIdx.x * blockDim.x + threadIdx.x;
    if (i < NN) { deg[i] = 0; indeg[i] = 0; }
    if (i < BBg) { smax[i] = 0u; den[i] = 0.f; cnt[i] = 0.f; }
    if (i < BBg * 64) pool[i] = 0.f;
}

// ---------------- graph normalization + CSR build ----------------
__global__ void k_hist(const int* __restrict__ key, int* cnt, int E) {
    int e = blockIdx.x * blockDim.x + threadIdx.x;
    if (e < E) atomicAdd(&cnt[key[e]], 1);
}
__global__ void k_node(const int* __restrict__ batch, const float* __restrict__ lmax,
                       const int* __restrict__ deg, float* dis, float* wdiag, int n) {
    int i = blockIdx.x * blockDim.x + threadIdx.x;
    if (i >= n) return;
    int d = deg[i];
    dis[i] = (d > 0) ? rsqrtf((float)d) : 0.f;
    wdiag[i] = 2.f / lmax[batch[i]] - 1.f;
}
__global__ void k_edgew(const int* __restrict__ src, const int* __restrict__ dst,
                        const int* __restrict__ batch, const float* __restrict__ lmax,
                        const float* __restrict__ dis, float* we, int E) {
    int e = blockIdx.x * blockDim.x + threadIdx.x;
    if (e >= E) return;
    int s = src[e];
    we[e] = -2.f * dis[s] * dis[dst[e]] / lmax[batch[s]];
}
// single-block exclusive scan of indeg -> rowptr (+ cursor copy)
__global__ __launch_bounds__(1024) void k_scan(const int* __restrict__ indeg,
                                               int* rowptr, int* cursor) {
    __shared__ int sh[1024];
    const int CH = (NN + 1023) / 1024;   // 98
    int t = threadIdx.x;
    int beg = t * CH;
    int end = beg + CH; if (end > NN) end = NN;
    if (beg > NN) beg = NN;
    int s = 0;
    for (int i = beg; i < end; i++) s += indeg[i];
    sh[t] = s;
    __syncthreads();
    // Hillis-Steele inclusive scan
    for (int off = 1; off < 1024; off <<= 1) {
        int v = (t >= off) ? sh[t - off] : 0;
        __syncthreads();
        sh[t] += v;
        __syncthreads();
    }
    int run = sh[t] - s;                  // exclusive prefix for this chunk
    for (int i = beg; i < end; i++) {
        rowptr[i] = run;
        cursor[i] = run;
        run += indeg[i];
    }
    if (t == 1023) rowptr[NN] = sh[1023];
}
// scatter edges into CSR slots keyed by dst; payload = (src bits, weight)
__global__ void k_scatter(const int* __restrict__ src, const int* __restrict__ dst,
                          const float* __restrict__ we, int* cursor, float2* ep, int E) {
    int e = blockIdx.x * blockDim.x + threadIdx.x;
    if (e >= E) return;
    int pos = atomicAdd(&cursor[dst[e]], 1);
    ep[pos] = make_float2(__int_as_float(src[e]), we[e]);
}

// W[k][i][j] (K=5 leading) -> Wcat[i][k*Fout + j]
__global__ void k_reshape(const float* __restrict__ W, float* Wc, int Fin, int Fout) {
    int idx = blockIdx.x * blockDim.x + threadIdx.x;
    int tot = 5 * Fin * Fout;
    if (idx >= tot) return;
    int j = idx % Fout;
    int t = idx / Fout;
    int i = t % Fin;
    int k = t / Fin;
    Wc[i * (5 * Fout) + k * Fout + j] = W[idx];
}

// ---------------- SGEMM: C[M,Nc] = reluA?(relu(A)):A  @ B ----------------
#define BM 128
#define BN 32
#define BK 32
__global__ __launch_bounds__(256) void k_sgemm(const float* __restrict__ A,
                                               const float* __restrict__ B,
                                               float* __restrict__ C,
                                               int M, int K, int Nc, int reluA) {
    __shared__ float As[BK][BM + 4];
    __shared__ float Bs[BK][BN];
    int bm = blockIdx.y * BM, bn = blockIdx.x * BN;
    int tid = threadIdx.x;
    int ty = tid >> 4;      // 0..15, rows (x8)
    int tx = tid & 15;      // 0..15, cols (x2)
    float acc[8][2];
#pragma unroll
    for (int r = 0; r < 8; r++) { acc[r][0] = 0.f; acc[r][1] = 0.f; }

    for (int k0 = 0; k0 < K; k0 += BK) {
#pragma unroll
        for (int i = 0; i < 16; i++) {
            int idx = tid + i * 256;
            int m = idx >> 5;      // /32
            int k = idx & 31;
            int gm = bm + m;
            float v = (gm < M) ? A[(size_t)gm * K + k0 + k] : 0.f;
            As[k][m] = reluA ? fmaxf(v, 0.f) : v;
        }
#pragma unroll
        for (int i = 0; i < 4; i++) {
            int idx = tid + i * 256;
            int k = idx >> 5;      // /BN
            int c = idx & 31;
            Bs[k][c] = B[(size_t)(k0 + k) * Nc + bn + c];
        }
        __syncthreads();
#pragma unroll
        for (int kk = 0; kk < BK; kk++) {
            const float4* ap = (const float4*)&As[kk][ty * 8];
            float4 a0 = ap[0], a1 = ap[1];
            const float2* bp = (const float2*)&Bs[kk][tx * 2];
            float2 bv = bp[0];
            float a[8] = {a0.x, a0.y, a0.z, a0.w, a1.x, a1.y, a1.z, a1.w};
#pragma unroll
            for (int r = 0; r < 8; r++) {
                acc[r][0] += a[r] * bv.x;
                acc[r][1] += a[r] * bv.y;
            }
        }
        __syncthreads();
    }
#pragma unroll
    for (int r = 0; r < 8; r++) {
        int gm = bm + ty * 8 + r;
        if (gm < M) {
            float2 v; v.x = acc[r][0]; v.y = acc[r][1];
            *(float2*)&C[(size_t)gm * Nc + bn + tx * 2] = v;
        }
    }
}

// ---------------- fused Clenshaw step (diag + CSR edge gather, no atomics) ----
// Each thread handles TWO consecutive float4s (8 floats) of one node:
//   - halves redundant ep-row reads (G=F4/2 lanes per node share the row walk)
//   - two independent LDG.128 chains per gathered source row (MLP 2x)
// out[n,q] = U[n,q] + alpha*( wdiag[n]*bc[n,q] + sum_{e: dst=n} w_e*bc[src_e,q] )
//            - bp[n,q] (+ bias[q])
template <int F4, bool HASP, bool HASB>
__global__ __launch_bounds__(256) void k_cheb(
    const float4* __restrict__ U, int us4,
    const float4* __restrict__ bc, int bs4,
    const float4* __restrict__ bp, int ps4,
    const float* __restrict__ wdiag,
    const float* __restrict__ bias,
    float alpha,
    const int* __restrict__ rowptr,
    const float2* __restrict__ ep,
    float4* __restrict__ out, int n)
{
    const int G = F4 / 2;                    // threads per node (4 or 8)
    int idx = blockIdx.x * blockDim.x + threadIdx.x;
    if (idx >= n * G) return;
    int nd = idx / G;
    int q  = (idx & (G - 1)) * 2;            // first float4 index of this thread's pair

    const float4* brow = bc + (size_t)nd * bs4 + q;
    float4 b0a = brow[0], b0b = brow[1];
    float wd = wdiag[nd];
    float4 accA, accB;
    accA.x = wd * b0a.x; accA.y = wd * b0a.y; accA.z = wd * b0a.z; accA.w = wd * b0a.w;
    accB.x = wd * b0b.x; accB.y = wd * b0b.y; accB.z = wd * b0b.z; accB.w = wd * b0b.w;

    int js = rowptr[nd], je = rowptr[nd + 1];
    for (int j = js; j < je; j++) {
        float2 p = __ldg(&ep[j]);
        int s = __float_as_int(p.x);
        float w = p.y;
        const float4* vrow = bc + (size_t)s * bs4 + q;
        float4 va = vrow[0], vb = vrow[1];
        accA.x = fmaf(w, va.x, accA.x);
        accA.y = fmaf(w, va.y, accA.y);
        accA.z = fmaf(w, va.z, accA.z);
        accA.w = fmaf(w, va.w, accA.w);
        accB.x = fmaf(w, vb.x, accB.x);
        accB.y = fmaf(w, vb.y, accB.y);
        accB.z = fmaf(w, vb.z, accB.z);
        accB.w = fmaf(w, vb.w, accB.w);
    }

    const float4* urow = U + (size_t)nd * us4 + q;
    float4 ua = urow[0], ub = urow[1];
    float4 ra, rb;
    ra.x = fmaf(alpha, accA.x, ua.x);
    ra.y = fmaf(alpha, accA.y, ua.y);
    ra.z = fmaf(alpha, accA.z, ua.z);
    ra.w = fmaf(alpha, accA.w, ua.w);
    rb.x = fmaf(alpha, accB.x, ub.x);
    rb.y = fmaf(alpha, accB.y, ub.y);
    rb.z = fmaf(alpha, accB.z, ub.z);
    rb.w = fmaf(alpha, accB.w, ub.w);
    if (HASP) {
        const float4* prow = bp + (size_t)nd * ps4 + q;
        float4 pa = prow[0], pb = prow[1];
        ra.x -= pa.x; ra.y -= pa.y; ra.z -= pa.z; ra.w -= pa.w;
        rb.x -= pb.x; rb.y -= pb.y; rb.z -= pb.z; rb.w -= pb.w;
    }
    if (HASB) {
        float4 ba = ((const float4*)bias)[q];
        float4 bbv = ((const float4*)bias)[q + 1];
        ra.x += ba.x; ra.y += ba.y; ra.z += ba.z; ra.w += ba.w;
        rb.x += bbv.x; rb.y += bbv.y; rb.z += bbv.z; rb.w += bbv.w;
    }
    out[(size_t)nd * F4 + q]     = ra;
    out[(size_t)nd * F4 + q + 1] = rb;
}

// ---------------- pooling ----------------
__global__ void k_score(const float4* __restrict__ cl4, const float* __restrict__ cw,
                        const float* __restrict__ cb, const int* __restrict__ batch,
                        float* s, unsigned* smax, int n) {
    int i = blockIdx.x * blockDim.x + threadIdx.x;
    if (i >= n) return;
    float acc = cb[0];
#pragma unroll
    for (int j = 0; j < 4; j++) {
        float4 c = cl4[i * 4 + j];
        acc += c.x * cw[j * 4 + 0] + c.y * cw[j * 4 + 1]
             + c.z * cw[j * 4 + 2] + c.w * cw[j * 4 + 3];
    }
    s[i] = acc;
    atomicMax(&smax[batch[i]], f2o(acc));
}
__global__ void k_exp(const float* __restrict__ s, const unsigned* __restrict__ smax,
                      const int* __restrict__ batch, float* se, float* den, float* cnt, int n) {
    int i = blockIdx.x * blockDim.x + threadIdx.x;
    if (i >= n) return;
    int b = batch[i];
    float e = expf(s[i] - o2f(smax[b]));
    se[i] = e;
    atomicAdd(&den[b], e);
    atomicAdd(&cnt[b], 1.f);
}
// weighted max pool; h is pre-relu layer-3 output, relu fused here.
// w >= 0 and relu(h) >= 0, so int-compare atomicMax on float bits is monotone
// (pool initialized to 0.0f which is also the relu lower bound).
__global__ void k_wmax(const float* __restrict__ se, const float* __restrict__ den,
                       const float* __restrict__ cnt, const int* __restrict__ batch,
                       const float4* __restrict__ h, int* pool, int n) {
    int idx = blockIdx.x * blockDim.x + threadIdx.x;  // n * 16 (F=64 -> 16 float4)
    if (idx >= n * 16) return;
    int nd = idx >> 4, q = idx & 15;
    int b = batch[nd];
    float w = se[nd] / den[b] * cnt[b];
    float4 v = h[(size_t)nd * 16 + q];
    v.x = fmaxf(v.x, 0.f); v.y = fmaxf(v.y, 0.f);
    v.z = fmaxf(v.z, 0.f); v.w = fmaxf(v.w, 0.f);
    int* p = pool + (b * 64 + q * 4);
    atomicMax(&p[0], __float_as_int(w * v.x));
    atomicMax(&p[1], __float_as_int(w * v.y));
    atomicMax(&p[2], __float_as_int(w * v.z));
    atomicMax(&p[3], __float_as_int(w * v.w));
}
__global__ void k_final(const float* __restrict__ pool, const float* __restrict__ a1w,
                        const float* __restrict__ a1b, const float* __restrict__ a2w,
                        const float* __restrict__ a2b, float* out) {
    int b = blockIdx.x * blockDim.x + threadIdx.x;
    if (b >= BBg) return;
    float acc = a2b[0];
#pragma unroll
    for (int j = 0; j < 16; j++) {
        float a = a1b[j];
#pragma unroll
        for (int f = 0; f < 64; f++) a += pool[b * 64 + f] * a1w[f * 16 + j];
        acc += fmaxf(a, 0.f) * a2w[j];
    }
    out[b] = acc;
}

// ---------------- per-layer Clenshaw driver (compile-time F4) ----------------
template <int F4>
static void run_layer_poly(const int* rowptr, const float2* ep,
                           const float* wdiag, const float* U,
                           float* bA, float* bB, float* bC,
                           const float* bias, float* Hout) {
    const int T = 256;
    const int C4 = 5 * F4;
    const int G = F4 / 2;
    int nodeBl = (NN * G + T - 1) / T;
    const float4* U4 = (const float4*)U;

    // b4 = U4 (view). b3 = U3 + 2 L b4
    k_cheb<F4, false, false><<<nodeBl, T>>>(U4 + 3 * F4, C4, U4 + 4 * F4, C4,
                                            nullptr, 0, wdiag, nullptr, 2.f,
                                            rowptr, ep, (float4*)bA, NN);
    // b2 = U2 + 2 L b3 - b4
    k_cheb<F4, true, false><<<nodeBl, T>>>(U4 + 2 * F4, C4, (const float4*)bA, F4,
                                           U4 + 4 * F4, C4, wdiag, nullptr, 2.f,
                                           rowptr, ep, (float4*)bB, NN);
    // b1 = U1 + 2 L b2 - b3
    k_cheb<F4, true, false><<<nodeBl, T>>>(U4 + 1 * F4, C4, (const float4*)bB, F4,
                                           (const float4*)bA, F4, wdiag, nullptr, 2.f,
                                           rowptr, ep, (float4*)bC, NN);
    // out = U0 + L b1 - b2 + bias (relu deferred to consumer)
    k_cheb<F4, true, true><<<nodeBl, T>>>(U4, C4, (const float4*)bC, F4,
                                          (const float4*)bB, F4, wdiag, bias, 1.f,
                                          rowptr, ep, (float4*)Hout, NN);
}

// ---------------- host orchestration ----------------
extern "C" void kernel_launch(void* const* d_in, const int* in_sizes, int n_in,
                              void* d_out, int out_size) {
    const float* x     = (const float*)d_in[0];
    const float* cl    = (const float*)d_in[1];
    const float* lmax  = (const float*)d_in[2];
    const int*   src   = (const int*)d_in[3];
    const int*   dst   = (const int*)d_in[4];
    const int*   batch = (const int*)d_in[5];
    const float* w1 = (const float*)d_in[6];  const float* b1 = (const float*)d_in[7];
    const float* w2 = (const float*)d_in[8];  const float* b2 = (const float*)d_in[9];
    const float* w3 = (const float*)d_in[10]; const float* b3 = (const float*)d_in[11];
    const float* cw = (const float*)d_in[12]; const float* cb = (const float*)d_in[13];
    const float* a1w = (const float*)d_in[14]; const float* a1b = (const float*)d_in[15];
    const float* a2w = (const float*)d_in[16]; const float* a2b = (const float*)d_in[17];
    float* out = (float*)d_out;

    // Resolve scratch addresses every call (no static caching — harness rules).
    float *U, *bA, *bB, *bC, *h1, *h2, *h3, *wedge, *wdiag, *dis;
    float *Wc1, *Wc2, *Wc3, *s, *se, *den, *cnt, *pool;
    float2* ep;
    int *deg, *indeg, *rowptr, *cursor; unsigned* smax;
    cudaGetSymbolAddress((void**)&U, g_U);
    cudaGetSymbolAddress((void**)&bA, g_bA);
    cudaGetSymbolAddress((void**)&bB, g_bB);
    cudaGetSymbolAddress((void**)&bC, g_bC);
    cudaGetSymbolAddress((void**)&h1, g_h1);
    cudaGetSymbolAddress((void**)&h2, g_h2);
    cudaGetSymbolAddress((void**)&h3, g_h3);
    cudaGetSymbolAddress((void**)&wedge, g_wedge);
    cudaGetSymbolAddress((void**)&wdiag, g_wdiag);
    cudaGetSymbolAddress((void**)&dis, g_dis);
    cudaGetSymbolAddress((void**)&deg, g_deg);
    cudaGetSymbolAddress((void**)&indeg, g_indeg);
    cudaGetSymbolAddress((void**)&rowptr, g_rowptr);
    cudaGetSymbolAddress((void**)&cursor, g_cursor);
    cudaGetSymbolAddress((void**)&ep, g_ep);
    cudaGetSymbolAddress((void**)&Wc1, g_Wc1);
    cudaGetSymbolAddress((void**)&Wc2, g_Wc2);
    cudaGetSymbolAddress((void**)&Wc3, g_Wc3);
    cudaGetSymbolAddress((void**)&s, g_s);
    cudaGetSymbolAddress((void**)&se, g_se);
    cudaGetSymbolAddress((void**)&smax, g_smax);
    cudaGetSymbolAddress((void**)&den, g_den);
    cudaGetSymbolAddress((void**)&cnt, g_cnt);
    cudaGetSymbolAddress((void**)&pool, g_pool);

    const int T = 256;

    // ---- graph norm + CSR precompute ----
    k_init<<<(NN + T - 1) / T, T>>>(deg, indeg, smax, den, cnt, pool);
    k_hist<<<(EE + T - 1) / T, T>>>(src, deg, EE);       // out-degree (normalization)
    k_hist<<<(EE + T - 1) / T, T>>>(dst, indeg, EE);     // in-degree (CSR)
    k_node<<<(NN + T - 1) / T, T>>>(batch, lmax, deg, dis, wdiag, NN);
    k_edgew<<<(EE + T - 1) / T, T>>>(src, dst, batch, lmax, dis, wedge, EE);
    k_scan<<<1, 1024>>>(indeg, rowptr, cursor);
    k_scatter<<<(EE + T - 1) / T, T>>>(src, dst, wedge, cursor, ep, EE);
    k_reshape<<<(5 * 128 * 32 + T - 1) / T, T>>>(w1, Wc1, 128, 32);
    k_reshape<<<(5 * 32 * 64 + T - 1) / T, T>>>(w2, Wc2, 32, 64);
    k_reshape<<<(5 * 64 * 64 + T - 1) / T, T>>>(w3, Wc3, 64, 64);

    // ---- layer 1: Fin=128, Fout=32 (F4=8) ----
    {
        dim3 gr(160 / BN, (NN + BM - 1) / BM);
        k_sgemm<<<gr, 256>>>(x, Wc1, U, NN, 128, 160, 0);
        run_layer_poly<8>(rowptr, ep, wdiag, U, bA, bB, bC, b1, h1);
    }
    // ---- layer 2: Fin=32, Fout=64 (F4=16); relu(h1) fused into GEMM read ----
    {
        dim3 gr(320 / BN, (NN + BM - 1) / BM);
        k_sgemm<<<gr, 256>>>(h1, Wc2, U, NN, 32, 320, 1);
        run_layer_poly<16>(rowptr, ep, wdiag, U, bA, bB, bC, b2, h2);
    }
    // ---- layer 3: Fin=64, Fout=64 (F4=16); relu(h2) fused into GEMM read ----
    {
        dim3 gr(320 / BN, (NN + BM - 1) / BM);
        k_sgemm<<<gr, 256>>>(h2, Wc3, U, NN, 64, 320, 1);
        run_layer_poly<16>(rowptr, ep, wdiag, U, bA, bB, bC, b3, h3);
    }

    // ---- pooling + head (relu(h3) fused into k_wmax) ----
    k_score<<<(NN + T - 1) / T, T>>>((const float4*)cl, cw, cb, batch, s, smax, NN);
    k_exp<<<(NN + T - 1) / T, T>>>(s, smax, batch, se, den, cnt, NN);
    k_wmax<<<(NN * 16 + T - 1) / T, T>>>(se, den, cnt, batch, (const float4*)h3,
                                         (int*)pool, NN);
    k_final<<<1, BBg>>>(pool, a1w, a1b, a2w, a2b, out);

    (void)in_sizes; (void)n_in; (void)out_size;
}